// round 16
// baseline (speedup 1.0000x reference)
#include <cuda_runtime.h>
#include <cstdint>

#define HH   480
#define WW   864
#define W4   216                 // WW/4
#define HW4  (HH*W4)             // 103680 float4 per sample
#define HWX  (HH*WW)
#define MAXB 224
#define FROWS 8                  // rows per fill tile
#define FBX  (HH/FROWS)          // 60 tiles per sample
#define NT   256
#define NBLK 296                 // 2 blocks/SM on 148 SMs -> co-resident

// Search results: single-owner writes, always overwritten before use.
__device__ int g_cnt [MAXB];
__device__ int g_minr[MAXB];
__device__ int g_maxr[MAXB];
__device__ int g_minc[MAXB];
__device__ int g_maxc[MAXB];
// Barrier state (reset by last exiting block each replay).
__device__ int          g_bar  = 0;
__device__ volatile int g_rel  = 0;
__device__ int          g_exit = 0;

__global__ __launch_bounds__(NT) void ram_fused(const float4* __restrict__ mask,
                                                const int* __restrict__ n_pts,
                                                const int* __restrict__ n_loose,
                                                float4* __restrict__ out,
                                                float* __restrict__ out_bbox,
                                                int B)
{
    const int t    = threadIdx.x;
    const int bid  = blockIdx.x;
    const int w    = t >> 5;
    const int lane = t & 31;
    const int thr   = *n_pts;
    const int loose = *n_loose;

    // ============ Phase 1: warp-per-task early-exit searches ============
    if (bid < B && w < 5) {
        const float4* base = mask + (size_t)bid * HW4;
        int result = 0;

        if (w == 0) {
            // count, early-out at >= thr (chunks of 32 float4 = 128 px)
            int total = 0;
            for (int start = 0; start < HW4; start += 32) {
                float4 v = base[start + lane];
                int c = (v.x > 0.5f) + (v.y > 0.5f) + (v.z > 0.5f) + (v.w > 0.5f);
                total += __reduce_add_sync(0xffffffffu, c);
                if (total >= thr) break;
            }
            result = total;
            if (lane == 0) g_cnt[bid] = result;
        } else if (w == 1) {
            // min_r: top-down; each lane covers 7 column groups
            result = HH;
            for (int r = 0; r < HH; r++) {
                bool hit = false;
                #pragma unroll
                for (int k = 0; k < 7; k++) {
                    int cg = lane + k * 32;
                    if (cg < W4) {
                        float4 v = base[(size_t)r * W4 + cg];
                        hit |= (fmaxf(fmaxf(v.x, v.y), fmaxf(v.z, v.w)) > 0.5f);
                    }
                }
                if (__any_sync(0xffffffffu, hit)) { result = r; break; }
            }
            if (lane == 0) g_minr[bid] = result;
        } else if (w == 2) {
            // max_r: bottom-up
            result = -1;
            for (int r = HH - 1; r >= 0; r--) {
                bool hit = false;
                #pragma unroll
                for (int k = 0; k < 7; k++) {
                    int cg = lane + k * 32;
                    if (cg < W4) {
                        float4 v = base[(size_t)r * W4 + cg];
                        hit |= (fmaxf(fmaxf(v.x, v.y), fmaxf(v.z, v.w)) > 0.5f);
                    }
                }
                if (__any_sync(0xffffffffu, hit)) { result = r; break; }
            }
            if (lane == 0) g_maxr[bid] = result;
        } else if (w == 3) {
            // min_c: left-to-right column-group probe (15 rows per lane)
            result = WW;
            for (int cg = 0; cg < W4; cg++) {
                int lm = 1 << 30;
                for (int r = lane; r < HH; r += 32) {
                    float4 v = base[(size_t)r * W4 + cg];
                    int cm = (v.x > 0.5f) ? 4*cg
                           : (v.y > 0.5f) ? 4*cg + 1
                           : (v.z > 0.5f) ? 4*cg + 2
                           : (v.w > 0.5f) ? 4*cg + 3 : (1 << 30);
                    lm = min(lm, cm);
                }
                lm = __reduce_min_sync(0xffffffffu, lm);
                if (lm < (1 << 30)) { result = lm; break; }
            }
            if (lane == 0) g_minc[bid] = result;
        } else {
            // max_c: right-to-left
            result = -1;
            for (int cg = W4 - 1; cg >= 0; cg--) {
                int lm = -1;
                for (int r = lane; r < HH; r += 32) {
                    float4 v = base[(size_t)r * W4 + cg];
                    int cm = (v.w > 0.5f) ? 4*cg + 3
                           : (v.z > 0.5f) ? 4*cg + 2
                           : (v.y > 0.5f) ? 4*cg + 1
                           : (v.x > 0.5f) ? 4*cg : -1;
                    lm = max(lm, cm);
                }
                lm = __reduce_max_sync(0xffffffffu, lm);
                if (lm >= 0) { result = lm; break; }
            }
            if (lane == 0) g_maxc[bid] = result;
        }
        if (lane == 0) __threadfence();   // publish this warp's result
    }
    __syncthreads();

    // ============ Global barrier (sense via release flag) ============
    __shared__ int s_go;
    if (t == 0) {
        if (atomicAdd(&g_bar, 1) == NBLK - 1) {
            __threadfence();
            g_rel = 1;                      // release all
        } else {
            while (g_rel == 0) __nanosleep(64);
        }
        __threadfence();                    // acquire: all results visible
        s_go = 1;
    }
    __syncthreads();

    // out_bbox tail (independent of fill)
    if (bid < B && t == 0 && out_bbox) {
        const bool full = g_cnt[bid] < thr;
        int y0 = full ? 0      : max(0, min(HH - 1, g_minr[bid] - loose));
        int y1 = full ? HH - 1 : max(0, min(HH - 1, g_maxr[bid] + loose));
        int x0 = full ? 0      : max(0, min(WW - 1, g_minc[bid] - loose));
        int x1 = full ? WW - 1 : max(0, min(WW - 1, g_maxc[bid] + loose));
        out_bbox[bid * 4 + 0] = (float)y0;
        out_bbox[bid * 4 + 1] = (float)y1;
        out_bbox[bid * 4 + 2] = (float)x0;
        out_bbox[bid * 4 + 3] = (float)x1;
    }

    // ============ Phase 2: strided fill tiles ============
    const int ntiles = B * FBX;
    __shared__ int4 sbb;
    __shared__ int  s_b;
    for (int tile = bid; tile < ntiles; tile += NBLK) {
        const int b = tile / FBX;
        const int x = tile - b * FBX;

        if (t == 0) {
            if (tile == bid || s_b != b) {      // finalize once per new sample
                const bool full = g_cnt[b] < thr;
                int y0 = full ? 0      : max(0, min(HH - 1, g_minr[b] - loose));
                int y1 = full ? HH - 1 : max(0, min(HH - 1, g_maxr[b] + loose));
                int x0 = full ? 0      : max(0, min(WW - 1, g_minc[b] - loose));
                int x1 = full ? WW - 1 : max(0, min(WW - 1, g_maxc[b] + loose));
                sbb = make_int4(y0, y1, x0, x1);
                s_b = b;
            }
        }
        __syncthreads();

        if (t < W4) {
            const int4 bb = sbb;
            const int r0 = x * FROWS;
            const int c = t * 4;
            float4 vin;
            vin.x = (c     >= bb.z && c     <= bb.w) ? 1.f : 0.f;
            vin.y = (c + 1 >= bb.z && c + 1 <= bb.w) ? 1.f : 0.f;
            vin.z = (c + 2 >= bb.z && c + 2 <= bb.w) ? 1.f : 0.f;
            vin.w = (c + 3 >= bb.z && c + 3 <= bb.w) ? 1.f : 0.f;
            const float4 vz = make_float4(0.f, 0.f, 0.f, 0.f);

            float4* p = out + (size_t)b * HW4 + (size_t)r0 * W4 + t;
            #pragma unroll
            for (int j = 0; j < FROWS; j++) {
                const int r = r0 + j;
                p[(size_t)j * W4] = (r >= bb.x && r <= bb.y) ? vin : vz;
            }
        }
        __syncthreads();
    }

    // ============ Reset (last block out) ============
    if (t == 0) {
        if (atomicAdd(&g_exit, 1) == NBLK - 1) {
            g_bar = 0;
            g_rel = 0;
            __threadfence();
            g_exit = 0;
        }
    }
    (void)s_go;
}

extern "C" void kernel_launch(void* const* d_in, const int* in_sizes, int n_in,
                              void* d_out, int out_size) {
    const float* mask = (const float*)d_in[0];
    const int* n_pts  = (const int*)d_in[1];
    const int* loose  = (const int*)d_in[2];
    float* out        = (float*)d_out;

    const int B = in_sizes[0] / HWX;
    const int att_elems = B * HWX;
    float* out_bbox = (out_size >= att_elems + 4 * B) ? (out + att_elems) : nullptr;

    ram_fused<<<NBLK, NT>>>((const float4*)mask, n_pts, loose,
                            (float4*)out, out_bbox, B);
}

// round 17
// speedup vs baseline: 1.1672x; 1.1672x over previous
#include <cuda_runtime.h>
#include <cstdint>

#define HH   480
#define WW   864
#define W4   216                 // WW/4
#define HW4  (HH*W4)             // 103680 float4 per sample
#define HWX  (HH*WW)
#define MAXB 224
#define FROWS 8                  // rows per fill block
#define FBX  (HH/FROWS)          // 60

__device__ int4 g_bbox[MAXB];

// ---------------------------------------------------------------------------
// Kernel A: grid (B), 160 threads = 5 warps, one early-exit search per warp.
// No block syncs inside the searches; all five probes' DRAM round-trips are
// concurrently in flight. Warp 0 finalizes after one __syncthreads.
// ---------------------------------------------------------------------------
__global__ __launch_bounds__(160) void ram_bbox(const float4* __restrict__ mask,
                                                const int* __restrict__ n_pts,
                                                const int* __restrict__ n_loose,
                                                float* __restrict__ out_bbox)
{
    const int t    = threadIdx.x;
    const int b    = blockIdx.x;
    const int w    = t >> 5;
    const int lane = t & 31;
    const float4* base = mask + (size_t)b * HW4;

    __shared__ int s_cnt, s_minr, s_maxr, s_minc, s_maxc;

    if (w == 0) {
        // ---- count, early-out at >= thr (32 float4 = 128 px per iter) ----
        const int thr = *n_pts;
        int total = 0;
        for (int start = 0; start < HW4; start += 32) {
            float4 v = base[start + lane];
            int c = (v.x > 0.5f) + (v.y > 0.5f) + (v.z > 0.5f) + (v.w > 0.5f);
            total += __reduce_add_sync(0xffffffffu, c);
            if (total >= thr) break;
        }
        if (lane == 0) s_cnt = total;
    } else if (w == 1) {
        // ---- min_r: top-down; each lane covers 7 column groups ----
        int res = HH;
        for (int r = 0; r < HH; r++) {
            bool hit = false;
            #pragma unroll
            for (int k = 0; k < 7; k++) {
                int cg = lane + k * 32;
                if (cg < W4) {
                    float4 v = base[(size_t)r * W4 + cg];
                    hit |= (fmaxf(fmaxf(v.x, v.y), fmaxf(v.z, v.w)) > 0.5f);
                }
            }
            if (__any_sync(0xffffffffu, hit)) { res = r; break; }
        }
        if (lane == 0) s_minr = res;
    } else if (w == 2) {
        // ---- max_r: bottom-up ----
        int res = -1;
        for (int r = HH - 1; r >= 0; r--) {
            bool hit = false;
            #pragma unroll
            for (int k = 0; k < 7; k++) {
                int cg = lane + k * 32;
                if (cg < W4) {
                    float4 v = base[(size_t)r * W4 + cg];
                    hit |= (fmaxf(fmaxf(v.x, v.y), fmaxf(v.z, v.w)) > 0.5f);
                }
            }
            if (__any_sync(0xffffffffu, hit)) { res = r; break; }
        }
        if (lane == 0) s_maxr = res;
    } else if (w == 3) {
        // ---- min_c: left-to-right column-group probe (15 rows/lane) ----
        int res = WW;
        for (int cg = 0; cg < W4; cg++) {
            int lm = 1 << 30;
            for (int r = lane; r < HH; r += 32) {
                float4 v = base[(size_t)r * W4 + cg];
                int cm = (v.x > 0.5f) ? 4*cg
                       : (v.y > 0.5f) ? 4*cg + 1
                       : (v.z > 0.5f) ? 4*cg + 2
                       : (v.w > 0.5f) ? 4*cg + 3 : (1 << 30);
                lm = min(lm, cm);
            }
            lm = __reduce_min_sync(0xffffffffu, lm);
            if (lm < (1 << 30)) { res = lm; break; }
        }
        if (lane == 0) s_minc = res;
    } else {
        // ---- max_c: right-to-left ----
        int res = -1;
        for (int cg = W4 - 1; cg >= 0; cg--) {
            int lm = -1;
            for (int r = lane; r < HH; r += 32) {
                float4 v = base[(size_t)r * W4 + cg];
                int cm = (v.w > 0.5f) ? 4*cg + 3
                       : (v.z > 0.5f) ? 4*cg + 2
                       : (v.y > 0.5f) ? 4*cg + 1
                       : (v.x > 0.5f) ? 4*cg : -1;
                lm = max(lm, cm);
            }
            lm = __reduce_max_sync(0xffffffffu, lm);
            if (lm >= 0) { res = lm; break; }
        }
        if (lane == 0) s_maxc = res;
    }

    __syncthreads();

    // Warp 0 lane 0 finalizes (shared-memory only; no global atomics).
    if (t == 0) {
        const int thr = *n_pts, loose = *n_loose;
        const bool full = s_cnt < thr;
        int y0 = full ? 0      : max(0, min(HH - 1, s_minr - loose));
        int y1 = full ? HH - 1 : max(0, min(HH - 1, s_maxr + loose));
        int x0 = full ? 0      : max(0, min(WW - 1, s_minc - loose));
        int x1 = full ? WW - 1 : max(0, min(WW - 1, s_maxc + loose));
        g_bbox[b] = make_int4(y0, y1, x0, x1);
        if (out_bbox) {
            out_bbox[b * 4 + 0] = (float)y0;
            out_bbox[b * 4 + 1] = (float)y1;
            out_bbox[b * 4 + 2] = (float)x0;
            out_bbox[b * 4 + 3] = (float)x1;
        }
    }
}

// ---------------------------------------------------------------------------
// Kernel B: lean fill (R2 shape): one L2-hot int4 read, 8 predicated stores.
// ---------------------------------------------------------------------------
__global__ __launch_bounds__(224) void ram_fill(float4* __restrict__ out)
{
    const int t = threadIdx.x;
    if (t >= W4) return;
    const int b  = blockIdx.y;
    const int r0 = blockIdx.x * FROWS;
    const int4 bb = g_bbox[b];

    const int c = t * 4;
    float4 vin;
    vin.x = (c     >= bb.z && c     <= bb.w) ? 1.f : 0.f;
    vin.y = (c + 1 >= bb.z && c + 1 <= bb.w) ? 1.f : 0.f;
    vin.z = (c + 2 >= bb.z && c + 2 <= bb.w) ? 1.f : 0.f;
    vin.w = (c + 3 >= bb.z && c + 3 <= bb.w) ? 1.f : 0.f;
    const float4 vz = make_float4(0.f, 0.f, 0.f, 0.f);

    float4* p = out + (size_t)b * HW4 + (size_t)r0 * W4 + t;
    #pragma unroll
    for (int j = 0; j < FROWS; j++) {
        const int r = r0 + j;
        p[(size_t)j * W4] = (r >= bb.x && r <= bb.y) ? vin : vz;
    }
}

extern "C" void kernel_launch(void* const* d_in, const int* in_sizes, int n_in,
                              void* d_out, int out_size) {
    const float* mask = (const float*)d_in[0];
    const int* n_pts  = (const int*)d_in[1];
    const int* loose  = (const int*)d_in[2];
    float* out        = (float*)d_out;

    const int B = in_sizes[0] / HWX;
    const int att_elems = B * HWX;
    float* out_bbox = (out_size >= att_elems + 4 * B) ? (out + att_elems) : nullptr;

    ram_bbox<<<B, 160>>>((const float4*)mask, n_pts, loose, out_bbox);
    ram_fill<<<dim3(FBX, B), 224>>>((float4*)out);
}